// round 1
// baseline (speedup 1.0000x reference)
#include <cuda_runtime.h>

#define N_NODES   50000
#define N_EDGES   800000
#define NUM_GRAPHS 512
#define F1 128
#define F2 64

// ---------------- scratch (device globals: allocation-free) ----------------
__device__ float g_deg[N_NODES];
__device__ float g_dinv[N_NODES];
__device__ float g_h1[(size_t)N_NODES * F1];
__device__ float g_agg1[(size_t)N_NODES * F1];
__device__ float g_h2[(size_t)N_NODES * F2];
__device__ float g_agg2[(size_t)N_NODES * F2];
__device__ float g_pool[NUM_GRAPHS * F2];
__device__ float g_cnt[NUM_GRAPHS];
__device__ int   g_src[N_EDGES];
__device__ int   g_dst[N_EDGES];
__device__ int   g_batch[N_NODES];
__device__ int   g_is64_edge;
__device__ int   g_is64_batch;

// ---------------- dtype detection (int64 vs int32 indices) ----------------
// If data is int64 (values >=0, < 2^31), every high dword is 0.
// If data is int32, sampled odd positions are random/near-511 values: nonzero whp.
__global__ void detect_kernel(const int* __restrict__ ei32,
                              const int* __restrict__ b32) {
    __shared__ int s_e, s_b;
    if (threadIdx.x == 0) { s_e = 0; s_b = 0; }
    __syncthreads();
    int t = threadIdx.x;
    long long ie = (long long)t * 3121 + 5;         // < N_EDGES, within bounds both ways
    if (ei32[2 * ie + 1] != 0) atomicOr(&s_e, 1);
    long long ib = N_NODES / 2 - 1 - t;             // tail of first-half elements
    if (b32[2 * ib + 1] != 0) atomicOr(&s_b, 1);
    __syncthreads();
    if (threadIdx.x == 0) {
        g_is64_edge  = s_e ? 0 : 1;
        g_is64_batch = s_b ? 0 : 1;
    }
}

// Normalize indices to int32 scratch; also init deg (self-loop=1) and zero pool/cnt.
__global__ void convert_init_kernel(const int* __restrict__ ei32,
                                    const int* __restrict__ b32) {
    int i = blockIdx.x * blockDim.x + threadIdx.x;
    int e64 = g_is64_edge, b64 = g_is64_batch;
    if (i < N_EDGES) {
        g_src[i] = e64 ? ei32[2 * (size_t)i]             : ei32[i];
        g_dst[i] = e64 ? ei32[2 * ((size_t)N_EDGES + i)] : ei32[N_EDGES + i];
    }
    if (i < N_NODES) {
        g_batch[i] = b64 ? b32[2 * (size_t)i] : b32[i];
        g_deg[i] = 1.0f;                       // self loop
    }
    if (i < NUM_GRAPHS * F2) g_pool[i] = 0.0f;
    if (i < NUM_GRAPHS)      g_cnt[i]  = 0.0f;
}

__global__ void deg_edges_kernel() {
    int e = blockIdx.x * blockDim.x + threadIdx.x;
    if (e < N_EDGES) atomicAdd(&g_deg[g_dst[e]], 1.0f);
}

__global__ void dinv_kernel() {
    int i = blockIdx.x * blockDim.x + threadIdx.x;
    if (i < N_NODES) g_dinv[i] = rsqrtf(g_deg[i]);   // deg >= 1 always
}

// ---------------- GEMM: C[M,N] = op(A[M,128]) @ W[128,N] ----------------
// Block: (N/4)*(BM/4) threads, each computes a 4x4 microtile.
// W fully resident in smem; A tile row-major in smem (pad 132 -> no conflicts,
// inner-loop A reads are warp-broadcast).
template <int N, int BM, bool RELU>
__global__ void gemm_kernel(const float* __restrict__ A,
                            const float* __restrict__ W,
                            float* __restrict__ C, int M) {
    constexpr int K  = 128;
    constexpr int XP = K + 4;                 // padded row stride (floats)
    constexpr int NT = (N / 4) * (BM / 4);
    extern __shared__ float sm[];
    float* Ws = sm;                            // K*N
    float* Xs = sm + K * N;                    // BM*XP

    int tid = threadIdx.x;
    // load W (float4, coalesced)
    const float4* W4 = (const float4*)W;
    float4* Ws4w = (float4*)Ws;
    #pragma unroll
    for (int idx = tid; idx < K * N / 4; idx += NT) Ws4w[idx] = W4[idx];

    // load A tile (row-major, coalesced float4; optional relu)
    int row0 = blockIdx.x * BM;
    for (int idx = tid; idx < BM * 32; idx += NT) {
        int r  = idx >> 5;          // row in tile
        int k4 = idx & 31;          // float4 within row
        int row = row0 + r;
        float4 v = make_float4(0.f, 0.f, 0.f, 0.f);
        if (row < M) v = ((const float4*)A)[(size_t)row * 32 + k4];
        if (RELU) {
            v.x = fmaxf(v.x, 0.f); v.y = fmaxf(v.y, 0.f);
            v.z = fmaxf(v.z, 0.f); v.w = fmaxf(v.w, 0.f);
        }
        *(float4*)&Xs[r * XP + k4 * 4] = v;
    }
    __syncthreads();

    int nc = tid % (N / 4);
    int rg = tid / (N / 4);
    float acc[4][4];
    #pragma unroll
    for (int i = 0; i < 4; i++)
        #pragma unroll
        for (int j = 0; j < 4; j++) acc[i][j] = 0.f;

    const float4* Ws4 = (const float4*)Ws;
    #pragma unroll 4
    for (int k = 0; k < K; k++) {
        float4 w = Ws4[k * (N / 4) + nc];
        float xr[4];
        #pragma unroll
        for (int i = 0; i < 4; i++) xr[i] = Xs[(rg * 4 + i) * XP + k];
        #pragma unroll
        for (int i = 0; i < 4; i++) {
            acc[i][0] += xr[i] * w.x;
            acc[i][1] += xr[i] * w.y;
            acc[i][2] += xr[i] * w.z;
            acc[i][3] += xr[i] * w.w;
        }
    }

    #pragma unroll
    for (int i = 0; i < 4; i++) {
        int row = row0 + rg * 4 + i;
        if (row < M) {
            float4 o = make_float4(acc[i][0], acc[i][1], acc[i][2], acc[i][3]);
            ((float4*)C)[(size_t)row * (N / 4) + nc] = o;
        }
    }
}

// ---------------- aggregation init: agg = bias + dinv^2 * h ----------------
template <int F>
__global__ void agg_init_kernel(const float* __restrict__ h,
                                const float* __restrict__ bias,
                                float* __restrict__ agg) {
    int idx = blockIdx.x * blockDim.x + threadIdx.x;   // over N_NODES*(F/4)
    if (idx >= N_NODES * (F / 4)) return;
    int node = idx / (F / 4);
    int f4   = idx % (F / 4);
    float d  = g_dinv[node];
    float d2 = d * d;
    float4 v = ((const float4*)h)[idx];
    float4 b = ((const float4*)bias)[f4];
    v.x = v.x * d2 + b.x;
    v.y = v.y * d2 + b.y;
    v.z = v.z * d2 + b.z;
    v.w = v.w * d2 + b.w;
    ((float4*)agg)[idx] = v;
}

__device__ __forceinline__ void red_add_v4(float* p, float4 v) {
    asm volatile("red.global.add.v4.f32 [%0], {%1,%2,%3,%4};"
                 :: "l"(p), "f"(v.x), "f"(v.y), "f"(v.z), "f"(v.w)
                 : "memory");
}

// ---------------- edge aggregation: agg[dst] += norm * h[src] ----------------
// 128 features: one warp per edge (32 lanes x float4)
__global__ void agg_edges128_kernel(const float* __restrict__ h,
                                    float* __restrict__ agg) {
    int gtid = blockIdx.x * blockDim.x + threadIdx.x;
    int e    = gtid >> 5;
    int lane = threadIdx.x & 31;
    if (e >= N_EDGES) return;
    int src = 0, dst = 0; float norm = 0.f;
    if (lane == 0) {
        src  = g_src[e];
        dst  = g_dst[e];
        norm = g_dinv[src] * g_dinv[dst];
    }
    src  = __shfl_sync(0xffffffffu, src, 0);
    dst  = __shfl_sync(0xffffffffu, dst, 0);
    norm = __shfl_sync(0xffffffffu, norm, 0);
    float4 v = ((const float4*)h)[(size_t)src * 32 + lane];
    v.x *= norm; v.y *= norm; v.z *= norm; v.w *= norm;
    red_add_v4(agg + (size_t)dst * 128 + lane * 4, v);
}

// 64 features: 16 lanes per edge
__global__ void agg_edges64_kernel(const float* __restrict__ h,
                                   float* __restrict__ agg) {
    int gtid = blockIdx.x * blockDim.x + threadIdx.x;
    int e    = gtid >> 4;
    int lane = threadIdx.x & 15;
    if (e >= N_EDGES) return;
    int src = 0, dst = 0; float norm = 0.f;
    if (lane == 0) {
        src  = g_src[e];
        dst  = g_dst[e];
        norm = g_dinv[src] * g_dinv[dst];
    }
    src  = __shfl_sync(0xffffffffu, src, 0, 16);
    dst  = __shfl_sync(0xffffffffu, dst, 0, 16);
    norm = __shfl_sync(0xffffffffu, norm, 0, 16);
    float4 v = ((const float4*)h)[(size_t)src * 16 + lane];
    v.x *= norm; v.y *= norm; v.z *= norm; v.w *= norm;
    red_add_v4(agg + (size_t)dst * 64 + lane * 4, v);
}

// ---------------- pooling: segment sums over batch ----------------
__global__ void pool_kernel() {
    int gtid = blockIdx.x * blockDim.x + threadIdx.x;
    int node = gtid >> 4;
    int lane = threadIdx.x & 15;
    if (node >= N_NODES) return;
    int g = 0;
    if (lane == 0) g = g_batch[node];
    g = __shfl_sync(0xffffffffu, g, 0, 16);
    float4 v = ((const float4*)g_agg2)[(size_t)node * 16 + lane];
    red_add_v4(g_pool + (size_t)g * 64 + lane * 4, v);
    if (lane == 0) atomicAdd(&g_cnt[g], 1.0f);
}

// ---------------- final: out = (pool / max(cnt,1)) @ Wl + bl ----------------
__global__ void final_kernel(const float* __restrict__ Wl,
                             const float* __restrict__ bl,
                             float* __restrict__ out) {
    int g = blockIdx.x;        // 512
    int n = threadIdx.x;       // 64
    __shared__ float ps[64];
    float inv = 1.0f / fmaxf(g_cnt[g], 1.0f);
    ps[n] = g_pool[g * 64 + n] * inv;
    __syncthreads();
    float acc = bl[n];
    #pragma unroll
    for (int k = 0; k < 64; k++) acc += ps[k] * Wl[k * 64 + n];
    out[g * 64 + n] = acc;
}

// ---------------- launch ----------------
extern "C" void kernel_launch(void* const* d_in, const int* in_sizes, int n_in,
                              void* d_out, int out_size) {
    const float* x    = (const float*)d_in[0];
    const int*   ei32 = (const int*)d_in[1];
    const int*   b32  = (const int*)d_in[2];
    const float* W1   = (const float*)d_in[3];
    const float* b1   = (const float*)d_in[4];
    const float* W2   = (const float*)d_in[5];
    const float* b2   = (const float*)d_in[6];
    const float* Wl   = (const float*)d_in[7];
    const float* bl   = (const float*)d_in[8];
    float* out = (float*)d_out;

    float *p_h1, *p_agg1, *p_h2, *p_agg2;
    cudaGetSymbolAddress((void**)&p_h1,   g_h1);
    cudaGetSymbolAddress((void**)&p_agg1, g_agg1);
    cudaGetSymbolAddress((void**)&p_h2,   g_h2);
    cudaGetSymbolAddress((void**)&p_agg2, g_agg2);

    const int SM_G1 = (128 * 128 + 32 * 132) * 4;   // 82432
    const int SM_G2 = (128 * 64 + 64 * 132) * 4;    // 66560
    cudaFuncSetAttribute((const void*)gemm_kernel<128, 32, false>,
                         cudaFuncAttributeMaxDynamicSharedMemorySize, SM_G1);
    cudaFuncSetAttribute((const void*)gemm_kernel<64, 64, true>,
                         cudaFuncAttributeMaxDynamicSharedMemorySize, SM_G2);

    // 1) dtype detection + index normalization + inits
    detect_kernel<<<1, 256>>>(ei32, b32);
    convert_init_kernel<<<(N_EDGES + 255) / 256, 256>>>(ei32, b32);

    // 2) degrees (A + I) and D^{-1/2}
    deg_edges_kernel<<<(N_EDGES + 255) / 256, 256>>>();
    dinv_kernel<<<(N_NODES + 255) / 256, 256>>>();

    // 3) layer 1: h1 = x @ W1 ; agg1 = b1 + norm-agg ; (relu fused into gemm2)
    gemm_kernel<128, 32, false><<<(N_NODES + 31) / 32, 256, SM_G1>>>(x, W1, p_h1, N_NODES);
    agg_init_kernel<128><<<(N_NODES * 32 + 255) / 256, 256>>>(p_h1, b1, p_agg1);
    agg_edges128_kernel<<<(N_EDGES * 32 + 255) / 256, 256>>>(p_h1, p_agg1);

    // 4) layer 2: h2 = relu(agg1) @ W2 ; agg2 = b2 + norm-agg
    gemm_kernel<64, 64, true><<<(N_NODES + 63) / 64, 256, SM_G2>>>(p_agg1, W2, p_h2, N_NODES);
    agg_init_kernel<64><<<(N_NODES * 16 + 255) / 256, 256>>>(p_h2, b2, p_agg2);
    agg_edges64_kernel<<<(N_EDGES * 16 + 255) / 256, 256>>>(p_h2, p_agg2);

    // 5) mean pool per graph + final linear
    pool_kernel<<<(N_NODES * 16 + 255) / 256, 256>>>();
    final_kernel<<<NUM_GRAPHS, 64>>>(Wl, bl, out);
}